// round 13
// baseline (speedup 1.0000x reference)
#include <cuda_runtime.h>
#include <cuda_fp16.h>
#include <cstdint>

// Problem shape (fixed by setup_inputs): B=32, S=256, H=768
#define NB 32
#define NS 256
#define NH 768
#define ROW_U4 (NH/8)   // 96 uint4 (fp16) per token row

// ---------------- scratch (static device globals; no allocation) ----------------
__device__ uint4  g_qn4[NB*NS*ROW_U4];   // normalized Q, fp16
__device__ uint4  g_kn4[NB*NS*ROW_U4];   // normalized K, fp16
__device__ uint4  g_Shl4[64*ROW_U4];     // S hi (rows 0..31) / lo (rows 32..63), fp16
__device__ float  g_wtab[NS];            // scale * exp(-alpha * d)
__device__ float  g_invden[NB];          // 1 / clip(sum q_mask, 1)
__device__ float  g_nvalid[NB];          // # valid key tokens per j
__device__ float  g_cntwin[NB*8];        // # valid keys in fast window per (j, st)
__device__ float  g_dotS[NB*NB*NS];      // [j][i*256+s] = q_row . S_j
__device__ float  g_bandN[2*NB*NB*NS];   // per (half,i,j,s) band numerator
__device__ float  g_bandD[2*NB*NB*NS];   // band denominator
__device__ float  g_bandS[2*NB*NB*NS];   // band sum of sims (valid only)
__device__ float  g_flagf;               // 1.0 if banded fast path valid else 0.0
__device__ int    g_nwin;                // 1 (fast) or 4 (full fallback)

// ---------------- helpers ----------------
static __device__ __forceinline__ uint32_t smem_u32(const void* p) {
    uint32_t a;
    asm("{ .reg .u64 t; cvta.to.shared.u64 t, %1; cvt.u32.u64 %0, t; }" : "=r"(a) : "l"(p));
    return a;
}
#define CP_ASYNC16(dst_s32, src_gen) \
    asm volatile("cp.async.cg.shared.global [%0], [%1], 16;" \
                 :: "r"(dst_s32), "l"(__cvta_generic_to_global(src_gen)) : "memory")
#define CP_COMMIT() asm volatile("cp.async.commit_group;" ::: "memory")
#define CP_WAIT(n)  asm volatile("cp.async.wait_group %0;" :: "n"(n) : "memory")
#define LDSM4(r0,r1,r2,r3,addr) \
    asm volatile("ldmatrix.sync.aligned.m8n8.x4.shared.b16 {%0,%1,%2,%3}, [%4];" \
                 : "=r"(r0), "=r"(r1), "=r"(r2), "=r"(r3) : "r"(addr))

static __device__ __forceinline__ void mma16816(float c[4],
                                                uint32_t a0, uint32_t a1, uint32_t a2, uint32_t a3,
                                                uint32_t b0, uint32_t b1) {
    asm volatile("mma.sync.aligned.m16n8k16.row.col.f32.f16.f16.f32 "
                 "{%0,%1,%2,%3}, {%4,%5,%6,%7}, {%8,%9}, {%0,%1,%2,%3};"
                 : "+f"(c[0]), "+f"(c[1]), "+f"(c[2]), "+f"(c[3])
                 : "r"(a0), "r"(a1), "r"(a2), "r"(a3), "r"(b0), "r"(b1));
}

// ---------------- kernel 1: scalars ----------------
__global__ void __launch_bounds__(256) prep_kernel(const float* __restrict__ ar,
                                                   const float* __restrict__ ls,
                                                   const float* __restrict__ qm,
                                                   const float* __restrict__ km) {
    int tid = threadIdx.x;
    float a = ar[0];
    float alpha = (a > 15.f) ? a : log1pf(expf(a));   // softplus
    float scale = expf(ls[0]);
    g_wtab[tid] = scale * expf(-alpha * (float)tid);
    if (tid == 0) {
        int fast = (scale * expf(-17.f * alpha) < 1e-8f) ? 1 : 0;
        g_flagf = fast ? 1.f : 0.f;
        g_nwin  = fast ? 1 : 4;
    }
    __shared__ float ws[8];
    for (int i = 0; i < NB; i++) {
        float v = qm[i*NS + tid];
        #pragma unroll
        for (int o = 16; o; o >>= 1) v += __shfl_xor_sync(0xffffffffu, v, o);
        if ((tid & 31) == 0) ws[tid >> 5] = v;
        __syncthreads();
        if (tid == 0) {
            float s = 0.f;
            #pragma unroll
            for (int w = 0; w < 8; w++) s += ws[w];
            g_invden[i] = 1.f / fmaxf(s, 1.f);
        }
        __syncthreads();
    }
    for (int j = 0; j < NB; j++) {
        float v = (km[j*NS + tid] > 0.f) ? 1.f : 0.f;
        #pragma unroll
        for (int o = 16; o; o >>= 1) v += __shfl_xor_sync(0xffffffffu, v, o);
        if ((tid & 31) == 0) ws[tid >> 5] = v;
        __syncthreads();
        if (tid == 0) {
            float s = 0.f;
            #pragma unroll
            for (int w = 0; w < 8; w++) s += ws[w];
            g_nvalid[j] = s;
        }
        __syncthreads();
    }
    // per-(j, st) fast-window valid counts
    {
        int j = tid >> 3, st = tid & 7;
        int t0 = min(max(st*32 - 16, 0), NS - 64);
        float c = 0.f;
        for (int r = 0; r < 64; r++)
            c += (km[j*NS + t0 + r] > 0.f) ? 1.f : 0.f;
        g_cntwin[j*8 + st] = c;
    }
}

// ---------------- kernel 2: L2-normalize -> fp16 ----------------
__global__ void __launch_bounds__(256) normalize_kernel(const float* __restrict__ q,
                                                        const float* __restrict__ k) {
    int row = blockIdx.x, tid = threadIdx.x;
    const float* src = blockIdx.y ? k : q;
    half* dst = (half*)(blockIdx.y ? g_kn4 : g_qn4);
    float x0 = src[row*NH + tid];
    float x1 = src[row*NH + 256 + tid];
    float x2 = src[row*NH + 512 + tid];
    float ss = x0*x0 + x1*x1 + x2*x2;
    #pragma unroll
    for (int o = 16; o; o >>= 1) ss += __shfl_xor_sync(0xffffffffu, ss, o);
    __shared__ float ws[8];
    __shared__ float s_inv;
    if ((tid & 31) == 0) ws[tid >> 5] = ss;
    __syncthreads();
    if (tid == 0) {
        float s = 0.f;
        #pragma unroll
        for (int w = 0; w < 8; w++) s += ws[w];
        s_inv = 1.f / fmaxf(sqrtf(s), 1e-12f);
    }
    __syncthreads();
    float inv = s_inv;
    dst[row*NH + tid]       = __float2half_rn(x0 * inv);
    dst[row*NH + 256 + tid] = __float2half_rn(x1 * inv);
    dst[row*NH + 512 + tid] = __float2half_rn(x2 * inv);
}

// ---------------- kernel 3: masked key sums -> hi/lo fp16 ----------------
__global__ void __launch_bounds__(128) ksum_kernel(const float* __restrict__ km) {
    int j = blockIdx.x;
    int h = blockIdx.y * 128 + threadIdx.x;
    const half* kh = (const half*)g_kn4;
    float a0 = 0.f, a1 = 0.f, a2 = 0.f, a3 = 0.f;
    #pragma unroll 4
    for (int t = 0; t < NS; t += 4) {
        float m0 = km[j*NS + t],     v0 = __half2float(kh[(j*NS + t)*NH + h]);
        float m1 = km[j*NS + t + 1], v1 = __half2float(kh[(j*NS + t + 1)*NH + h]);
        float m2 = km[j*NS + t + 2], v2 = __half2float(kh[(j*NS + t + 2)*NH + h]);
        float m3 = km[j*NS + t + 3], v3 = __half2float(kh[(j*NS + t + 3)*NH + h]);
        if (m0 > 0.f) a0 += v0;
        if (m1 > 0.f) a1 += v1;
        if (m2 > 0.f) a2 += v2;
        if (m3 > 0.f) a3 += v3;
    }
    float s = (a0 + a1) + (a2 + a3);
    half hi = __float2half_rn(s);
    half lo = __float2half_rn(s - __half2float(hi));
    half* Shl = (half*)g_Shl4;
    Shl[j*NH + h]          = hi;
    Shl[(32 + j)*NH + h]   = lo;
}

// ---------------- kernel 4 (launch slot 4): persistent banded GEMM ----------------
// CTA = (st 0..7, i 0..31) = 256 CTAs, 512 threads = 16 warps.
// Warp grid 2(M) x 8(N), warp tile 16x32 over 4 j's (256 B-rows) per pass.
// PERIOD = K-chunk of 128 halves: 6 periods/pass, 48 total (fast path).
// 2-stage smem pipeline + REGISTER fragment double-buffering (LDSM of ks+1
// overlaps mma of ks — breaks the per-warp LDSM->mma scoreboard stall).
#define APITCH  1552
#define BPITCH  272                      // 128 halves + 8 pad
#define OFF_WT  0
#define OFF_A   2048
#define A_BYTES (32*APITCH)              // 49664
#define OFF_B   52224
#define B_STAGE (256*BPITCH)             // 69632
#define B_SMEM  (OFF_B + 2*B_STAGE)     // 191488

__global__ void __launch_bounds__(512, 1) li_band(const float* __restrict__ qmask,
                                                  const float* __restrict__ kmask) {
    extern __shared__ __align__(1024) char smem[];
    const int tid  = threadIdx.x;
    const int lane = tid & 31, wid = tid >> 5;
    const int wm = wid >> 3, wn = wid & 7;            // 2 x 8
    const int lr = lane >> 2;
    const int st = blockIdx.x, i = blockIdx.y;
    const int m0 = st * 32;

    float* wtab_s = (float*)(smem + OFF_WT);
    const uint32_t sb = smem_u32(smem);

    for (int c2 = tid; c2 < NS; c2 += 512) wtab_s[c2] = g_wtab[c2];

    const int nwin  = g_nwin;                          // 1 (fast) or 4
    const int t0f   = min(max(m0 - 16, 0), NS - 64);
    const int NG    = 8 * nwin;                        // window passes (4 j each)
    const int NP    = NG * 6;                          // pipeline periods

    // A resident load (32 x 768 halves); joins period-0's commit group
    {
        uint32_t sA = sb + OFF_A;
        const int qrow0 = i*NS + m0;
        #pragma unroll
        for (int w = 0; w < 6; w++) {                  // 3072 u4
            int idx = tid + w*512;
            int r = idx / 96, v = idx - r*96;
            CP_ASYNC16(sA + (uint32_t)(r*APITCH + v*16),
                       &g_qn4[(qrow0 + r)*ROW_U4 + v]);
        }
    }

    const int lq = lane >> 3, l7 = lane & 7;
    const uint32_t aOff = (uint32_t)(((lq & 1)*8 + l7)*APITCH + (lq >> 1)*16);
    const uint32_t bOff = (uint32_t)(((lq >> 1)*8 + l7)*BPITCH + (lq & 1)*16);
    const uint32_t sA0  = sb + OFF_A + (uint32_t)(wm*16)*APITCH + aOff;

    // period loader: p -> (g = p/6, kc = p%6); loads 256 rows x 256 bytes
    auto loadB = [&](int p) {
        int g = p / 6, kc = p - g*6;
        int jbase = (nwin == 1) ? g*4 : (g >> 2)*4;
        int t0    = (nwin == 1) ? t0f : (g & 3)*64;
        uint32_t sB = sb + OFF_B + (uint32_t)(p & 1)*B_STAGE;
        #pragma unroll
        for (int w = 0; w < 8; w++) {                  // 4096 u4
            int idx = tid + w*512, r = idx >> 4, v = idx & 15;
            int srow = (jbase + (r >> 6))*NS + t0 + (r & 63);
            CP_ASYNC16(sB + (uint32_t)(r*BPITCH + v*16),
                       &g_kn4[srow*ROW_U4 + kc*16 + v]);
        }
        CP_COMMIT();
    };

    float cfrag[4][4];
    #pragma unroll
    for (int ni = 0; ni < 4; ni++)
        #pragma unroll
        for (int r = 0; r < 4; r++) cfrag[ni][r] = 0.f;
    float num[2] = {0.f, 0.f}, den[2] = {0.f, 0.f}, ssim[2] = {0.f, 0.f};

    loadB(0);                                          // commits A + period 0

    for (int p = 0; p < NP; p++) {
        CP_WAIT(0);                                    // period p's data landed
        __syncthreads();                               // visible to all warps
        if (p + 1 < NP) loadB(p + 1);                  // other stage

        const int g = p / 6, kc = p - g*6;
        const uint32_t sAc = sA0 + (uint32_t)(kc*256);
        const uint32_t sBc = sb + OFF_B + (uint32_t)(p & 1)*B_STAGE
                           + (uint32_t)(wn*32)*BPITCH + bOff;

        // -------- register-double-buffered fragment mainloop --------
        uint32_t afr[2][4], bfr[2][2][4];
        LDSM4(afr[0][0], afr[0][1], afr[0][2], afr[0][3], sAc);
        LDSM4(bfr[0][0][0], bfr[0][0][1], bfr[0][0][2], bfr[0][0][3], sBc);
        LDSM4(bfr[0][1][0], bfr[0][1][1], bfr[0][1][2], bfr[0][1][3],
              sBc + (uint32_t)(16*BPITCH));
        #pragma unroll
        for (int ks = 0; ks < 8; ks++) {
            const int cur = ks & 1, nxt = cur ^ 1;
            if (ks < 7) {
                const uint32_t ko = (uint32_t)((ks + 1)*32);
                LDSM4(afr[nxt][0], afr[nxt][1], afr[nxt][2], afr[nxt][3],
                      sAc + ko);
                LDSM4(bfr[nxt][0][0], bfr[nxt][0][1], bfr[nxt][0][2], bfr[nxt][0][3],
                      sBc + ko);
                LDSM4(bfr[nxt][1][0], bfr[nxt][1][1], bfr[nxt][1][2], bfr[nxt][1][3],
                      sBc + (uint32_t)(16*BPITCH) + ko);
            }
            #pragma unroll
            for (int ni = 0; ni < 4; ni++)
                mma16816(cfrag[ni],
                         afr[cur][0], afr[cur][1], afr[cur][2], afr[cur][3],
                         bfr[cur][ni >> 1][(ni & 1)*2],
                         bfr[cur][ni >> 1][(ni & 1)*2 + 1]);
        }

        if (kc == 5) {                                 // end of window pass g
            const int jbase = (nwin == 1) ? g*4 : (g >> 2)*4;
            const int t0    = (nwin == 1) ? t0f : (g & 3)*64;
            const int j     = jbase + (wn >> 1);
            const int th    = (wn & 1);                // t-half 0/1
            #pragma unroll
            for (int rh = 0; rh < 2; rh++) {
                const int s_tok = m0 + wm*16 + 8*rh + lr;
                #pragma unroll
                for (int ni = 0; ni < 4; ni++) {
                    #pragma unroll
                    for (int rl = 0; rl < 2; rl++) {
                        float sim = cfrag[ni][rh*2 + rl];
                        int t = t0 + th*32 + ni*8 + (lane & 3)*2 + rl;
                        bool vld = __ldg(&kmask[j*NS + t]) > 0.f;
                        int d = (s_tok > t) ? (s_tok - t) : (t - s_tok);
                        float e = vld ? __expf(wtab_s[d] * sim) : 0.f;
                        num[rh] = fmaf(e, sim, num[rh]);
                        den[rh] += e;
                        if (vld) ssim[rh] += sim;
                    }
                }
            }
            #pragma unroll
            for (int ni = 0; ni < 4; ni++)
                #pragma unroll
                for (int r = 0; r < 4; r++) cfrag[ni][r] = 0.f;

            const bool last_nw = (nwin == 1) || ((g & 3) == 3);
            if (last_nw) {
                #pragma unroll
                for (int o = 1; o <= 2; o <<= 1) {
                    #pragma unroll
                    for (int rh = 0; rh < 2; rh++) {
                        num[rh]  += __shfl_xor_sync(0xffffffffu, num[rh],  o);
                        den[rh]  += __shfl_xor_sync(0xffffffffu, den[rh],  o);
                        ssim[rh] += __shfl_xor_sync(0xffffffffu, ssim[rh], o);
                    }
                }
                if ((lane & 3) == 0) {
                    #pragma unroll
                    for (int rh = 0; rh < 2; rh++) {
                        int s_tok = m0 + wm*16 + 8*rh + lr;
                        int base = th*(NB*NB*NS) + (i*NB + j)*NS + s_tok;
                        g_bandN[base] = num[rh];
                        g_bandD[base] = den[rh];
                        g_bandS[base] = ssim[rh];
                    }
                }
                num[0]=num[1]=den[0]=den[1]=ssim[0]=ssim[1]=0.f;
            }
        }
    }
}

// ---------------- kernel 5: dotS via tensor GEMM ----------------
#define DPITCH   144
#define D_ABYTES (128*DPITCH)
#define D_STAGE  (192*DPITCH)
#define D_OFF    1024
#define D_SMEM   (D_OFF + 3*D_STAGE)

__global__ void __launch_bounds__(256, 1) dots_mma() {
    extern __shared__ __align__(1024) char smem[];
    const int tid  = threadIdx.x;
    const int lane = tid & 31, wid = tid >> 5;
    const int wm = wid >> 1, wn = wid & 1;
    const int lr = lane >> 2;
    const int row0 = blockIdx.x * 128;
    const uint32_t sb = smem_u32(smem);

    const int lq = lane >> 3, l7 = lane & 7;
    const uint32_t aOff = (uint32_t)(((lq & 1)*8 + l7)*DPITCH + (lq >> 1)*16);
    const uint32_t bOff = (uint32_t)(((lq >> 1)*8 + l7)*DPITCH + (lq & 1)*16);

    auto loadC = [&](int kc, int sgi) {
        uint32_t sA = sb + D_OFF + sgi*D_STAGE;
        uint32_t sB = sA + D_ABYTES;
        #pragma unroll
        for (int w = 0; w < 4; w++) {
            int idx = tid + w*256, r = idx >> 3, v = idx & 7;
            CP_ASYNC16(sA + (uint32_t)(r*DPITCH + v*16),
                       &g_qn4[(row0 + r)*ROW_U4 + kc*8 + v]);
        }
        #pragma unroll
        for (int w = 0; w < 2; w++) {
            int idx = tid + w*256, r = idx >> 3, v = idx & 7;
            CP_ASYNC16(sB + (uint32_t)(r*DPITCH + v*16),
                       &g_Shl4[r*ROW_U4 + kc*8 + v]);
        }
        CP_COMMIT();
    };

    float c[2][4][4];
    #pragma unroll
    for (int mi = 0; mi < 2; mi++)
        #pragma unroll
        for (int ni = 0; ni < 4; ni++)
            #pragma unroll
            for (int r = 0; r < 4; r++) c[mi][ni][r] = 0.f;

    loadC(0, 0); loadC(1, 1);
    for (int kc = 0; kc < 12; kc++) {
        if (kc < 11) CP_WAIT(1); else CP_WAIT(0);
        __syncthreads();
        if (kc + 2 < 12) loadC(kc + 2, (kc + 2) % 3);

        const uint32_t sA = sb + D_OFF + (kc % 3)*D_STAGE + (uint32_t)(wm*32)*DPITCH + aOff;
        const uint32_t sB = sb + D_OFF + (kc % 3)*D_STAGE + D_ABYTES + (uint32_t)(wn*32)*DPITCH + bOff;
        #pragma unroll
        for (int ks = 0; ks < 4; ks++) {
            const uint32_t ko = ks*32;
            uint32_t a[2][4], bb[2][4];
            #pragma unroll
            for (int mi = 0; mi < 2; mi++)
                LDSM4(a[mi][0], a[mi][1], a[mi][2], a[mi][3],
                      sA + (uint32_t)(mi*16)*DPITCH + ko);
            #pragma unroll
            for (int nb = 0; nb < 2; nb++)
                LDSM4(bb[nb][0], bb[nb][1], bb[nb][2], bb[nb][3],
                      sB + (uint32_t)(nb*16)*DPITCH + ko);
            #pragma unroll
            for (int mi = 0; mi < 2; mi++)
                #pragma unroll
                for (int ni = 0; ni < 4; ni++)
                    mma16816(c[mi][ni], a[mi][0], a[mi][1], a[mi][2], a[mi][3],
                             bb[ni >> 1][(ni & 1)*2], bb[ni >> 1][(ni & 1)*2 + 1]);
        }
    }
    __syncthreads();

    float* o = (float*)(smem + D_OFF);               // [128][64]
    #pragma unroll
    for (int mi = 0; mi < 2; mi++)
        #pragma unroll
        for (int ni = 0; ni < 4; ni++)
            #pragma unroll
            for (int rh = 0; rh < 2; rh++)
                #pragma unroll
                for (int rl = 0; rl < 2; rl++) {
                    int r = wm*32 + mi*16 + 8*rh + lr;
                    int col = wn*32 + ni*8 + (lane & 3)*2 + rl;
                    o[r*64 + col] = c[mi][ni][rh*2 + rl];
                }
    __syncthreads();
    {
        int r = tid >> 1, j0 = (tid & 1)*16;
        #pragma unroll
        for (int k2 = 0; k2 < 16; k2++) {
            int j = j0 + k2;
            g_dotS[j*(NB*NS) + row0 + r] = o[r*64 + j] + o[r*64 + 32 + j];
        }
    }
}

// ---------------- kernel 6: score (correction + reduce, deterministic) ----------------
__global__ void __launch_bounds__(256) score_kernel(float* __restrict__ out,
                                                    const float* __restrict__ qmask) {
    const int j = blockIdx.x, i = blockIdx.y;
    const int s = threadIdx.x;
    const float flag = g_flagf;
    const int base = (i*NB + j)*NS + s;
    const int H = NB*NB*NS;
    float n  = g_bandN[base] + g_bandN[H + base];
    float d  = g_bandD[base] + g_bandD[H + base];
    float ss = g_bandS[base] + g_bandS[H + base];
    int st = s >> 5;
    float dden = d + flag * (g_nvalid[j] - g_cntwin[j*8 + st]);
    float dnum = n + flag * (g_dotS[j*(NB*NS) + i*NS + s] - ss);
    float sc = (dden > 0.f) ? (dnum / dden) * qmask[i*NS + s] : 0.f;
    #pragma unroll
    for (int o = 16; o; o >>= 1) sc += __shfl_xor_sync(0xffffffffu, sc, o);
    __shared__ float ws[8];
    if ((s & 31) == 0) ws[s >> 5] = sc;
    __syncthreads();
    if (s == 0) {
        float t = 0.f;
        #pragma unroll
        for (int w = 0; w < 8; w++) t += ws[w];
        out[i*NB + j] = t * g_invden[i];
    }
}

// ---------------- launch ----------------
extern "C" void kernel_launch(void* const* d_in, const int* in_sizes, int n_in,
                              void* d_out, int out_size) {
    const float* q  = (const float*)d_in[0];
    const float* k  = (const float*)d_in[1];
    const float* qm = (const float*)d_in[2];
    const float* km = (const float*)d_in[3];
    const float* ar = (const float*)d_in[4];
    const float* ls = (const float*)d_in[5];
    float* out = (float*)d_out;

    prep_kernel<<<1, 256>>>(ar, ls, qm, km);
    normalize_kernel<<<dim3(NB*NS, 2), 256>>>(q, k);
    ksum_kernel<<<dim3(NB, 6), 128>>>(km);

    static int smem_set = 0;
    if (!smem_set) {
        cudaFuncSetAttribute(li_band,  cudaFuncAttributeMaxDynamicSharedMemorySize, B_SMEM);
        cudaFuncSetAttribute(dots_mma, cudaFuncAttributeMaxDynamicSharedMemorySize, D_SMEM);
        smem_set = 1;
    }
    li_band<<<dim3(8, NB), 512, B_SMEM>>>(qm, km);     // 4th launch -> ncu slot
    dots_mma<<<64, 256, D_SMEM>>>();
    score_kernel<<<dim3(NB, NB), 256>>>(out, qm);
}

// round 14
// speedup vs baseline: 1.1571x; 1.1571x over previous
#include <cuda_runtime.h>
#include <cuda_fp16.h>
#include <cstdint>

// Problem shape (fixed by setup_inputs): B=32, S=256, H=768
#define NB 32
#define NS 256
#define NH 768
#define ROW_U4 (NH/8)   // 96 uint4 (fp16) per token row

// ---------------- scratch (static device globals; no allocation) ----------------
__device__ uint4  g_qn4[NB*NS*ROW_U4];   // normalized Q, fp16
__device__ uint4  g_kn4[NB*NS*ROW_U4];   // normalized K, fp16
__device__ uint4  g_Shl4[64*ROW_U4];     // S hi (rows 0..31) / lo (rows 32..63), fp16
__device__ float  g_wtab[NS];            // scale * exp(-alpha * d)
__device__ float  g_invden[NB];          // 1 / clip(sum q_mask, 1)
__device__ float  g_nvalid[NB];          // # valid key tokens per j
__device__ float  g_cntwin[NB*8];        // # valid keys in fast window per (j, st)
__device__ float  g_dotS[NB*NB*NS];      // [j][i*256+s] = q_row . S_j
__device__ float  g_bandN[2*NB*NB*NS];   // per (half,i,j,s) band numerator
__device__ float  g_bandD[2*NB*NB*NS];   // band denominator
__device__ float  g_bandS[2*NB*NB*NS];   // band sum of sims (valid only)
__device__ float  g_flagf;               // 1.0 if banded fast path valid else 0.0
__device__ int    g_nwin;                // 1 (fast) or 4 (full fallback)

// ---------------- helpers ----------------
static __device__ __forceinline__ uint32_t smem_u32(const void* p) {
    uint32_t a;
    asm("{ .reg .u64 t; cvta.to.shared.u64 t, %1; cvt.u32.u64 %0, t; }" : "=r"(a) : "l"(p));
    return a;
}
#define CP_ASYNC16(dst_s32, src_gen) \
    asm volatile("cp.async.cg.shared.global [%0], [%1], 16;" \
                 :: "r"(dst_s32), "l"(__cvta_generic_to_global(src_gen)) : "memory")
#define CP_COMMIT() asm volatile("cp.async.commit_group;" ::: "memory")
#define CP_WAIT(n)  asm volatile("cp.async.wait_group %0;" :: "n"(n) : "memory")
#define LDSM4(r0,r1,r2,r3,addr) \
    asm volatile("ldmatrix.sync.aligned.m8n8.x4.shared.b16 {%0,%1,%2,%3}, [%4];" \
                 : "=r"(r0), "=r"(r1), "=r"(r2), "=r"(r3) : "r"(addr))

static __device__ __forceinline__ void mma16816(float c[4],
                                                uint32_t a0, uint32_t a1, uint32_t a2, uint32_t a3,
                                                uint32_t b0, uint32_t b1) {
    asm volatile("mma.sync.aligned.m16n8k16.row.col.f32.f16.f16.f32 "
                 "{%0,%1,%2,%3}, {%4,%5,%6,%7}, {%8,%9}, {%0,%1,%2,%3};"
                 : "+f"(c[0]), "+f"(c[1]), "+f"(c[2]), "+f"(c[3])
                 : "r"(a0), "r"(a1), "r"(a2), "r"(a3), "r"(b0), "r"(b1));
}

// ---------------- kernel 1: scalars (parallel, no serial loops) ----------------
__global__ void __launch_bounds__(256) prep_kernel(const float* __restrict__ ar,
                                                   const float* __restrict__ ls,
                                                   const float* __restrict__ qm,
                                                   const float* __restrict__ km) {
    int tid = threadIdx.x, lane = tid & 31, wid = tid >> 5;
    float a = ar[0];
    float alpha = (a > 15.f) ? a : log1pf(expf(a));   // softplus
    float scale = expf(ls[0]);
    g_wtab[tid] = scale * expf(-alpha * (float)tid);
    if (tid == 0) {
        int fast = (scale * expf(-17.f * alpha) < 1e-8f) ? 1 : 0;
        g_flagf = fast ? 1.f : 0.f;
        g_nwin  = fast ? 1 : 4;
    }
    // each warp owns 4 rows; lane-strided sums (mask sums are exact integers)
    #pragma unroll
    for (int r = 0; r < 4; r++) {
        int row = wid*4 + r;
        float v = 0.f, u = 0.f;
        #pragma unroll
        for (int c = 0; c < 8; c++) {
            v += qm[row*NS + lane + c*32];
            u += (km[row*NS + lane + c*32] > 0.f) ? 1.f : 0.f;
        }
        #pragma unroll
        for (int o = 16; o; o >>= 1) {
            v += __shfl_xor_sync(0xffffffffu, v, o);
            u += __shfl_xor_sync(0xffffffffu, u, o);
        }
        if (lane == 0) {
            g_invden[row] = 1.f / fmaxf(v, 1.f);
            g_nvalid[row] = u;
        }
    }
    // per-(j, st) fast-window valid counts
    {
        int j = tid >> 3, st = tid & 7;
        int t0 = min(max(st*32 - 16, 0), NS - 64);
        float c = 0.f;
        #pragma unroll 8
        for (int r = 0; r < 64; r++)
            c += (km[j*NS + t0 + r] > 0.f) ? 1.f : 0.f;
        g_cntwin[j*8 + st] = c;
    }
}

// ---------------- kernel 2: L2-normalize -> fp16 ----------------
__global__ void __launch_bounds__(256) normalize_kernel(const float* __restrict__ q,
                                                        const float* __restrict__ k) {
    int row = blockIdx.x, tid = threadIdx.x;
    const float* src = blockIdx.y ? k : q;
    half* dst = (half*)(blockIdx.y ? g_kn4 : g_qn4);
    float x0 = src[row*NH + tid];
    float x1 = src[row*NH + 256 + tid];
    float x2 = src[row*NH + 512 + tid];
    float ss = x0*x0 + x1*x1 + x2*x2;
    #pragma unroll
    for (int o = 16; o; o >>= 1) ss += __shfl_xor_sync(0xffffffffu, ss, o);
    __shared__ float ws[8];
    __shared__ float s_inv;
    if ((tid & 31) == 0) ws[tid >> 5] = ss;
    __syncthreads();
    if (tid == 0) {
        float s = 0.f;
        #pragma unroll
        for (int w = 0; w < 8; w++) s += ws[w];
        s_inv = 1.f / fmaxf(sqrtf(s), 1e-12f);
    }
    __syncthreads();
    float inv = s_inv;
    dst[row*NH + tid]       = __float2half_rn(x0 * inv);
    dst[row*NH + 256 + tid] = __float2half_rn(x1 * inv);
    dst[row*NH + 512 + tid] = __float2half_rn(x2 * inv);
}

// ---------------- kernel 3: masked key sums -> hi/lo fp16 (MLP-8) ----------------
__global__ void __launch_bounds__(128) ksum_kernel(const float* __restrict__ km) {
    int j = blockIdx.x;
    int h = blockIdx.y * 128 + threadIdx.x;
    const half* kh = (const half*)g_kn4;
    float acc[8] = {0.f,0.f,0.f,0.f,0.f,0.f,0.f,0.f};
    for (int t = 0; t < NS; t += 8) {
        float m[8], v[8];
        #pragma unroll
        for (int u = 0; u < 8; u++) {
            m[u] = km[j*NS + t + u];
            v[u] = __half2float(kh[(j*NS + t + u)*NH + h]);
        }
        #pragma unroll
        for (int u = 0; u < 8; u++)
            if (m[u] > 0.f) acc[u] += v[u];
    }
    float s = ((acc[0]+acc[1]) + (acc[2]+acc[3])) + ((acc[4]+acc[5]) + (acc[6]+acc[7]));
    half hi = __float2half_rn(s);
    half lo = __float2half_rn(s - __half2float(hi));
    half* Shl = (half*)g_Shl4;
    Shl[j*NH + h]          = hi;
    Shl[(32 + j)*NH + h]   = lo;
}

// ---------------- kernel 4 (launch slot 4): persistent banded GEMM (R9 best) ------
// CTA = (st 0..7, i 0..31) = 256 CTAs, 512 threads = 16 warps.
// Warp grid 2(M) x 8(N), warp tile 16x32; wn>>1 = local j, wn&1 = t-half.
// A (32x768) resident once; 8 j-group passes, flattened 3-stage pipeline.
#define APITCH  1552
#define BPITCH  144
#define OFF_WT  0
#define OFF_QM  1024
#define OFF_KM  2048                     // 32 x 256 f32 = 32768
#define OFF_A   34816
#define A_BYTES (32*APITCH)              // 49664
#define OFF_B   (OFF_A + A_BYTES)        // 84480
#define B_STAGE (256*BPITCH)             // 36864
#define B_SMEM  (OFF_B + 3*B_STAGE)      // 195072

__global__ void __launch_bounds__(512, 1) li_band(const float* __restrict__ qmask,
                                                  const float* __restrict__ kmask) {
    extern __shared__ __align__(1024) char smem[];
    const int tid  = threadIdx.x;
    const int lane = tid & 31, wid = tid >> 5;
    const int wm = wid >> 3, wn = wid & 7;            // 2 x 8
    const int lr = lane >> 2;
    const int st = blockIdx.x, i = blockIdx.y;
    const int m0 = st * 32;

    float* wtab_s = (float*)(smem + OFF_WT);
    float* km_s   = (float*)(smem + OFF_KM);
    const uint32_t sb = smem_u32(smem);

    for (int c2 = tid; c2 < NS; c2 += 512) wtab_s[c2] = g_wtab[c2];
    for (int c2 = tid; c2 < NB*NS; c2 += 512) km_s[c2] = kmask[c2];

    const int nwin  = g_nwin;                          // 1 (fast) or 4
    const int t0f   = min(max(m0 - 16, 0), NS - 64);
    const int NG    = 8 * nwin;
    const int NCH   = NG * 12;

    // A resident load (32 x 768 halves); joins chunk-0's commit group
    {
        uint32_t sA = sb + OFF_A;
        const int qrow0 = i*NS + m0;
        #pragma unroll
        for (int w = 0; w < 6; w++) {                  // 3072 u4
            int idx = tid + w*512;
            int r = idx / 96, v = idx - r*96;
            CP_ASYNC16(sA + (uint32_t)(r*APITCH + v*16),
                       &g_qn4[(qrow0 + r)*ROW_U4 + v]);
        }
    }

    const int lq = lane >> 3, l7 = lane & 7;
    const uint32_t aOff = (uint32_t)(((lq & 1)*8 + l7)*APITCH + (lq >> 1)*16);
    const uint32_t bOff = (uint32_t)(((lq >> 1)*8 + l7)*BPITCH + (lq & 1)*16);

    auto loadB = [&](int c, int sgi) {
        int g = c / 12, kc = c - g*12;
        int jbase = (nwin == 1) ? g*4 : (g >> 2)*4;
        int t0    = (nwin == 1) ? t0f : (g & 3)*64;
        uint32_t sB = sb + OFF_B + sgi*B_STAGE;
        #pragma unroll
        for (int w = 0; w < 4; w++) {                  // 2048 u4
            int idx = tid + w*512, r = idx >> 3, v = idx & 7;
            int srow = (jbase + (r >> 6))*NS + t0 + (r & 63);
            CP_ASYNC16(sB + (uint32_t)(r*BPITCH + v*16),
                       &g_kn4[srow*ROW_U4 + kc*8 + v]);
        }
        CP_COMMIT();
    };

    float cfrag[4][4];
    #pragma unroll
    for (int ni = 0; ni < 4; ni++)
        #pragma unroll
        for (int r = 0; r < 4; r++) cfrag[ni][r] = 0.f;
    float num[2] = {0.f, 0.f}, den[2] = {0.f, 0.f}, ssim[2] = {0.f, 0.f};

    loadB(0, 0);                                       // commits A + chunk0
    loadB(1, 1);

    for (int c = 0; c < NCH; c++) {
        if (c < NCH-1) CP_WAIT(1); else CP_WAIT(0);
        __syncthreads();
        if (c + 2 < NCH) loadB(c + 2, (c + 2) % 3);

        const int g = c / 12, kc = c - g*12;
        const uint32_t sAc = sb + OFF_A + (uint32_t)(wm*16)*APITCH + aOff
                           + (uint32_t)(kc*128);
        const uint32_t sBc = sb + OFF_B + (uint32_t)(c % 3)*B_STAGE
                           + (uint32_t)(wn*32)*BPITCH + bOff;
        #pragma unroll
        for (int ks = 0; ks < 4; ks++) {
            const uint32_t ko = ks*32;
            uint32_t a0,a1,a2,a3;
            LDSM4(a0,a1,a2,a3, sAc + ko);
            uint32_t bb[2][4];
            #pragma unroll
            for (int nb = 0; nb < 2; nb++)
                LDSM4(bb[nb][0], bb[nb][1], bb[nb][2], bb[nb][3],
                      sBc + (uint32_t)(nb*16)*BPITCH + ko);
            #pragma unroll
            for (int ni = 0; ni < 4; ni++)
                mma16816(cfrag[ni], a0,a1,a2,a3,
                         bb[ni >> 1][(ni & 1)*2], bb[ni >> 1][(ni & 1)*2 + 1]);
        }

        if (kc == 11) {                                // end of window pass g
            const int jbase = (nwin == 1) ? g*4 : (g >> 2)*4;
            const int t0    = (nwin == 1) ? t0f : (g & 3)*64;
            const int j     = jbase + (wn >> 1);
            const int th    = (wn & 1);                // t-half 0/1
            #pragma unroll
            for (int rh = 0; rh < 2; rh++) {
                const int s_tok = m0 + wm*16 + 8*rh + lr;
                #pragma unroll
                for (int ni = 0; ni < 4; ni++) {
                    #pragma unroll
                    for (int rl = 0; rl < 2; rl++) {
                        float sim = cfrag[ni][rh*2 + rl];
                        int t = t0 + th*32 + ni*8 + (lane & 3)*2 + rl;
                        bool vld = km_s[j*NS + t] > 0.f;
                        int d = (s_tok > t) ? (s_tok - t) : (t - s_tok);
                        float e = vld ? __expf(wtab_s[d] * sim) : 0.f;
                        num[rh] = fmaf(e, sim, num[rh]);
                        den[rh] += e;
                        if (vld) ssim[rh] += sim;
                    }
                }
            }
            #pragma unroll
            for (int ni = 0; ni < 4; ni++)
                #pragma unroll
                for (int r = 0; r < 4; r++) cfrag[ni][r] = 0.f;

            const bool last_nw = (nwin == 1) || ((g & 3) == 3);
            if (last_nw) {
                #pragma unroll
                for (int o = 1; o <= 2; o <<= 1) {
                    #pragma unroll
                    for (int rh = 0; rh < 2; rh++) {
                        num[rh]  += __shfl_xor_sync(0xffffffffu, num[rh],  o);
                        den[rh]  += __shfl_xor_sync(0xffffffffu, den[rh],  o);
                        ssim[rh] += __shfl_xor_sync(0xffffffffu, ssim[rh], o);
                    }
                }
                if ((lane & 3) == 0) {
                    #pragma unroll
                    for (int rh = 0; rh < 2; rh++) {
                        int s_tok = m0 + wm*16 + 8*rh + lr;
                        int base = th*(NB*NB*NS) + (i*NB + j)*NS + s_tok;
                        g_bandN[base] = num[rh];
                        g_bandD[base] = den[rh];
                        g_bandS[base] = ssim[rh];
                    }
                }
                num[0]=num[1]=den[0]=den[1]=ssim[0]=ssim[1]=0.f;
            }
        }
    }
}

// ---------------- kernel 5: dotS via tensor GEMM ----------------
#define DPITCH   144
#define D_ABYTES (128*DPITCH)
#define D_STAGE  (192*DPITCH)
#define D_OFF    1024
#define D_SMEM   (D_OFF + 3*D_STAGE)

__global__ void __launch_bounds__(256, 1) dots_mma() {
    extern __shared__ __align__(1024) char smem[];
    const int tid  = threadIdx.x;
    const int lane = tid & 31, wid = tid >> 5;
    const int wm = wid >> 1, wn = wid & 1;
    const int lr = lane >> 2;
    const int row0 = blockIdx.x * 128;
    const uint32_t sb = smem_u32(smem);

    const int lq = lane >> 3, l7 = lane & 7;
    const uint32_t aOff = (uint32_t)(((lq & 1)*8 + l7)*DPITCH + (lq >> 1)*16);
    const uint32_t bOff = (uint32_t)(((lq >> 1)*8 + l7)*DPITCH + (lq & 1)*16);

    auto loadC = [&](int kc, int sgi) {
        uint32_t sA = sb + D_OFF + sgi*D_STAGE;
        uint32_t sB = sA + D_ABYTES;
        #pragma unroll
        for (int w = 0; w < 4; w++) {
            int idx = tid + w*256, r = idx >> 3, v = idx & 7;
            CP_ASYNC16(sA + (uint32_t)(r*DPITCH + v*16),
                       &g_qn4[(row0 + r)*ROW_U4 + kc*8 + v]);
        }
        #pragma unroll
        for (int w = 0; w < 2; w++) {
            int idx = tid + w*256, r = idx >> 3, v = idx & 7;
            CP_ASYNC16(sB + (uint32_t)(r*DPITCH + v*16),
                       &g_Shl4[r*ROW_U4 + kc*8 + v]);
        }
        CP_COMMIT();
    };

    float c[2][4][4];
    #pragma unroll
    for (int mi = 0; mi < 2; mi++)
        #pragma unroll
        for (int ni = 0; ni < 4; ni++)
            #pragma unroll
            for (int r = 0; r < 4; r++) c[mi][ni][r] = 0.f;

    loadC(0, 0); loadC(1, 1);
    for (int kc = 0; kc < 12; kc++) {
        if (kc < 11) CP_WAIT(1); else CP_WAIT(0);
        __syncthreads();
        if (kc + 2 < 12) loadC(kc + 2, (kc + 2) % 3);

        const uint32_t sA = sb + D_OFF + (kc % 3)*D_STAGE + (uint32_t)(wm*32)*DPITCH + aOff;
        const uint32_t sB = sb + D_OFF + (kc % 3)*D_STAGE + D_ABYTES + (uint32_t)(wn*32)*DPITCH + bOff;
        #pragma unroll
        for (int ks = 0; ks < 4; ks++) {
            const uint32_t ko = ks*32;
            uint32_t a[2][4], bb[2][4];
            #pragma unroll
            for (int mi = 0; mi < 2; mi++)
                LDSM4(a[mi][0], a[mi][1], a[mi][2], a[mi][3],
                      sA + (uint32_t)(mi*16)*DPITCH + ko);
            #pragma unroll
            for (int nb = 0; nb < 2; nb++)
                LDSM4(bb[nb][0], bb[nb][1], bb[nb][2], bb[nb][3],
                      sB + (uint32_t)(nb*16)*DPITCH + ko);
            #pragma unroll
            for (int mi = 0; mi < 2; mi++)
                #pragma unroll
                for (int ni = 0; ni < 4; ni++)
                    mma16816(c[mi][ni], a[mi][0], a[mi][1], a[mi][2], a[mi][3],
                             bb[ni >> 1][(ni & 1)*2], bb[ni >> 1][(ni & 1)*2 + 1]);
        }
    }
    __syncthreads();

    float* o = (float*)(smem + D_OFF);               // [128][64]
    #pragma unroll
    for (int mi = 0; mi < 2; mi++)
        #pragma unroll
        for (int ni = 0; ni < 4; ni++)
            #pragma unroll
            for (int rh = 0; rh < 2; rh++)
                #pragma unroll
                for (int rl = 0; rl < 2; rl++) {
                    int r = wm*32 + mi*16 + 8*rh + lr;
                    int col = wn*32 + ni*8 + (lane & 3)*2 + rl;
                    o[r*64 + col] = c[mi][ni][rh*2 + rl];
                }
    __syncthreads();
    {
        int r = tid >> 1, j0 = (tid & 1)*16;
        #pragma unroll
        for (int k2 = 0; k2 < 16; k2++) {
            int j = j0 + k2;
            g_dotS[j*(NB*NS) + row0 + r] = o[r*64 + j] + o[r*64 + 32 + j];
        }
    }
}

// ---------------- kernel 6: score (correction + reduce, deterministic) ----------------
__global__ void __launch_bounds__(256) score_kernel(float* __restrict__ out,
                                                    const float* __restrict__ qmask) {
    const int j = blockIdx.x, i = blockIdx.y;
    const int s = threadIdx.x;
    const float flag = g_flagf;
    const int base = (i*NB + j)*NS + s;
    const int H = NB*NB*NS;
    float n  = g_bandN[base] + g_bandN[H + base];
    float d  = g_bandD[base] + g_bandD[H + base];
    float ss = g_bandS[base] + g_bandS[H + base];
    int st = s >> 5;
    float dden = d + flag * (g_nvalid[j] - g_cntwin[j*8 + st]);
    float dnum = n + flag * (g_dotS[j*(NB*NS) + i*NS + s] - ss);
    float sc = (dden > 0.f) ? (dnum / dden) * qmask[i*NS + s] : 0.f;
    #pragma unroll
    for (int o = 16; o; o >>= 1) sc += __shfl_xor_sync(0xffffffffu, sc, o);
    __shared__ float ws[8];
    if ((s & 31) == 0) ws[s >> 5] = sc;
    __syncthreads();
    if (s == 0) {
        float t = 0.f;
        #pragma unroll
        for (int w = 0; w < 8; w++) t += ws[w];
        out[i*NB + j] = t * g_invden[i];
    }
}

// ---------------- launch ----------------
extern "C" void kernel_launch(void* const* d_in, const int* in_sizes, int n_in,
                              void* d_out, int out_size) {
    const float* q  = (const float*)d_in[0];
    const float* k  = (const float*)d_in[1];
    const float* qm = (const float*)d_in[2];
    const float* km = (const float*)d_in[3];
    const float* ar = (const float*)d_in[4];
    const float* ls = (const float*)d_in[5];
    float* out = (float*)d_out;

    prep_kernel<<<1, 256>>>(ar, ls, qm, km);
    normalize_kernel<<<dim3(NB*NS, 2), 256>>>(q, k);
    ksum_kernel<<<dim3(NB, 6), 128>>>(km);

    static int smem_set = 0;
    if (!smem_set) {
        cudaFuncSetAttribute(li_band,  cudaFuncAttributeMaxDynamicSharedMemorySize, B_SMEM);
        cudaFuncSetAttribute(dots_mma, cudaFuncAttributeMaxDynamicSharedMemorySize, D_SMEM);
        smem_set = 1;
    }
    li_band<<<dim3(8, NB), 512, B_SMEM>>>(qm, km);     // 4th launch -> ncu slot
    dots_mma<<<64, 256, D_SMEM>>>();
    score_kernel<<<dim3(NB, NB), 256>>>(out, qm);
}